// round 2
// baseline (speedup 1.0000x reference)
#include <cuda_runtime.h>
#include <math.h>

#define NA 15000
#define NE 300000
#define FF 128
#define NRBF 20
#define NL 3
#define CUTOFF 5.0f
#define PI_F 3.14159265358979f

// ---------------- static scratch (no allocations allowed) ----------------
__device__ float g_dir[NE * 3];
__device__ float g_phis[NE * NRBF];   // phi * fcut
__device__ float g_fcut[NE];
__device__ float g_x[NA * 384];
__device__ float g_h[NA * 128];
__device__ float g_ctx[NA * 256];
__device__ float g_mumix[NA * 3 * 256];
__device__ float g_dmu[NA * 3 * 128];

// ---------------- edge geometry: dir, phi*fcut, fcut ----------------
__global__ void geom_kernel(const float* __restrict__ rij) {
    int e = blockIdx.x * blockDim.x + threadIdx.x;
    if (e >= NE) return;
    float r0 = rij[e * 3 + 0], r1 = rij[e * 3 + 1], r2 = rij[e * 3 + 2];
    float d = sqrtf(r0 * r0 + r1 * r1 + r2 * r2);
    float inv = 1.0f / d;
    g_dir[e * 3 + 0] = r0 * inv;
    g_dir[e * 3 + 1] = r1 * inv;
    g_dir[e * 3 + 2] = r2 * inv;
    float fc = (d < CUTOFF) ? 0.5f * (cosf(d * PI_F / CUTOFF) + 1.0f) : 0.0f;
    g_fcut[e] = fc;
    const float width = CUTOFF / (NRBF - 1);
    const float coeff = -0.5f / (width * width);
#pragma unroll
    for (int k = 0; k < NRBF; k++) {
        float t = d - width * k;
        g_phis[e * NRBF + k] = expf(coeff * t * t) * fc;
    }
}

// ---------------- init q from embedding, zero mu & dmu ----------------
__global__ void init_kernel(const int* __restrict__ z, const float* __restrict__ emb,
                            float* __restrict__ q, float* __restrict__ mu) {
    int i = blockIdx.x * blockDim.x + threadIdx.x;
    if (i >= NA * 3 * FF) return;
    mu[i] = 0.0f;
    g_dmu[i] = 0.0f;
    if (i < NA * FF) {
        int a = i >> 7, f = i & 127;
        q[i] = emb[z[a] * FF + f];
    }
}

// ---------------- fused filter + edge message kernel ----------------
// Per thread: the 3xNRBF filter-weight slice for its feature lives in registers.
// Per edge: compute filters from phi (3 dot products), gather x[j], mu[j],
// scatter-add into q (dq) and g_dmu (dmu). Reads PRE-update mu (dmu buffered).
__global__ void __launch_bounds__(128) edge_kernel(const float* __restrict__ W,
                                                   const float* __restrict__ b,
                                                   int layer,
                                                   const int* __restrict__ idx_i,
                                                   const int* __restrict__ idx_j,
                                                   const float* __restrict__ mu,
                                                   float* __restrict__ q) {
    int f = threadIdx.x;
    float w0[NRBF], w1[NRBF], w2[NRBF];
#pragma unroll
    for (int k = 0; k < NRBF; k++) {
        const float* row = W + k * (NL * 384) + layer * 384;
        w0[k] = row[f];
        w1[k] = row[128 + f];
        w2[k] = row[256 + f];
    }
    float b0 = b[layer * 384 + f];
    float b1v = b[layer * 384 + 128 + f];
    float b2v = b[layer * 384 + 256 + f];

    for (int e = blockIdx.x; e < NE; e += gridDim.x) {
        const float* p = g_phis + e * NRBF;
        float a0 = 0.f, a1 = 0.f, a2 = 0.f;
#pragma unroll
        for (int k = 0; k < NRBF; k++) {
            float pk = __ldg(p + k);
            a0 += pk * w0[k];
            a1 += pk * w1[k];
            a2 += pk * w2[k];
        }
        float fc = __ldg(g_fcut + e);
        a0 += b0 * fc;
        a1 += b1v * fc;
        a2 += b2v * fc;

        int i = __ldg(idx_i + e), j = __ldg(idx_j + e);
        const float* xj = g_x + j * 384;
        float dq   = a0 * xj[f];
        float dmuR = a1 * xj[128 + f];
        float dmm  = a2 * xj[256 + f];
        float d0 = __ldg(g_dir + e * 3 + 0);
        float d1 = __ldg(g_dir + e * 3 + 1);
        float d2 = __ldg(g_dir + e * 3 + 2);
        const float* mj = mu + j * 3 * 128;
        atomicAdd(q + i * 128 + f, dq);
        atomicAdd(g_dmu + (i * 3 + 0) * 128 + f, dmuR * d0 + dmm * mj[f]);
        atomicAdd(g_dmu + (i * 3 + 1) * 128 + f, dmuR * d1 + dmm * mj[128 + f]);
        atomicAdd(g_dmu + (i * 3 + 2) * 128 + f, dmuR * d2 + dmm * mj[256 + f]);
    }
}

// ---------------- fold dmu into mu, re-zero dmu ----------------
__global__ void addmu_kernel(float* __restrict__ mu) {
    int i = blockIdx.x * blockDim.x + threadIdx.x;
    if (i >= NA * 3 * FF) return;
    mu[i] += g_dmu[i];
    g_dmu[i] = 0.0f;
}

// ---------------- generic SGEMM: C = act(A@B + bias) ----------------
// A: (M,K) row-major, B: (K,N) row-major, bias: (N). N mult of 64, K mult of 16.
__global__ void __launch_bounds__(256) sgemm_kernel(const float* __restrict__ A,
                                                    const float* __restrict__ B,
                                                    const float* __restrict__ bias,
                                                    float* __restrict__ C,
                                                    int M, int N, int K, int act) {
    __shared__ float As[16][64];
    __shared__ float Bs[16][64];
    int tid = threadIdx.x;
    int tx = tid & 15, ty = tid >> 4;
    int row0 = blockIdx.y * 64, col0 = blockIdx.x * 64;
    float acc[4][4] = {};
    int am = tid >> 2, ak = (tid & 3) * 4;
    int bk = tid >> 4, bn = (tid & 15) * 4;

    for (int k0 = 0; k0 < K; k0 += 16) {
        float4 av;
        int ar = row0 + am;
        if (ar < M) av = *(const float4*)(A + (size_t)ar * K + k0 + ak);
        else av = make_float4(0.f, 0.f, 0.f, 0.f);
        As[ak + 0][am] = av.x;
        As[ak + 1][am] = av.y;
        As[ak + 2][am] = av.z;
        As[ak + 3][am] = av.w;
        float4 bv = *(const float4*)(B + (size_t)(k0 + bk) * N + col0 + bn);
        *(float4*)&Bs[bk][bn] = bv;
        __syncthreads();
#pragma unroll
        for (int kk = 0; kk < 16; kk++) {
            float4 a4 = *(const float4*)&As[kk][ty * 4];
            float4 b4 = *(const float4*)&Bs[kk][tx * 4];
            float aa[4] = {a4.x, a4.y, a4.z, a4.w};
            float bb[4] = {b4.x, b4.y, b4.z, b4.w};
#pragma unroll
            for (int i = 0; i < 4; i++)
#pragma unroll
                for (int j = 0; j < 4; j++)
                    acc[i][j] += aa[i] * bb[j];
        }
        __syncthreads();
    }
#pragma unroll
    for (int i = 0; i < 4; i++) {
        int r = row0 + ty * 4 + i;
        if (r < M) {
            float4 o;
            float* op = (float*)&o;
#pragma unroll
            for (int j = 0; j < 4; j++) {
                float v = acc[i][j] + bias[col0 + tx * 4 + j];
                if (act) v = v / (1.0f + expf(-v));
                op[j] = v;
            }
            *(float4*)(C + (size_t)r * N + col0 + tx * 4) = o;
        }
    }
}

// ---------------- ctx = [q, ||mu_V||] ----------------
__global__ void ctx_kernel(const float* __restrict__ q) {
    int i = blockIdx.x * blockDim.x + threadIdx.x;
    if (i >= NA * FF) return;
    int a = i >> 7, f = i & 127;
    float v0 = g_mumix[(a * 3 + 0) * 256 + f];
    float v1 = g_mumix[(a * 3 + 1) * 256 + f];
    float v2 = g_mumix[(a * 3 + 2) * 256 + f];
    g_ctx[a * 256 + f] = q[i];
    g_ctx[a * 256 + 128 + f] = sqrtf(v0 * v0 + v1 * v1 + v2 * v2);
}

// ---------------- intra update of q and mu ----------------
__global__ void update_kernel(float* __restrict__ q, float* __restrict__ mu) {
    int i = blockIdx.x * blockDim.x + threadIdx.x;
    if (i >= NA * FF) return;
    int a = i >> 7, f = i & 127;
    float s = 0.0f;
    float xmu = g_x[a * 384 + 128 + f];
#pragma unroll
    for (int d = 0; d < 3; d++) {
        float mv = g_mumix[(a * 3 + d) * 256 + f];
        float mw = g_mumix[(a * 3 + d) * 256 + 128 + f];
        s += mv * mw;
        mu[(a * 3 + d) * 128 + f] += xmu * mw;
    }
    q[i] += g_x[a * 384 + f] + g_x[a * 384 + 256 + f] * s;
}

// ---------------- launcher ----------------
extern "C" void kernel_launch(void* const* d_in, const int* in_sizes, int n_in,
                              void* d_out, int out_size) {
    const float* r_ij      = (const float*)d_in[0];
    const float* embedding = (const float*)d_in[1];
    const float* filt_W    = (const float*)d_in[2];
    const float* filt_b    = (const float*)d_in[3];
    const float* inter_W1  = (const float*)d_in[4];
    const float* inter_b1  = (const float*)d_in[5];
    const float* inter_W2  = (const float*)d_in[6];
    const float* inter_b2  = (const float*)d_in[7];
    const float* mix_W     = (const float*)d_in[8];
    const float* mix_b     = (const float*)d_in[9];
    const float* intra_W1  = (const float*)d_in[10];
    const float* intra_b1  = (const float*)d_in[11];
    const float* intra_W2  = (const float*)d_in[12];
    const float* intra_b2  = (const float*)d_in[13];
    const int*   z         = (const int*)d_in[14];
    const int*   idx_i     = (const int*)d_in[15];
    const int*   idx_j     = (const int*)d_in[16];

    float* q  = (float*)d_out;
    float* mu = q + (size_t)NA * FF;

    void *p_h, *p_x, *p_ctx, *p_mumix;
    cudaGetSymbolAddress(&p_h, g_h);
    cudaGetSymbolAddress(&p_x, g_x);
    cudaGetSymbolAddress(&p_ctx, g_ctx);
    cudaGetSymbolAddress(&p_mumix, g_mumix);
    float* hbuf  = (float*)p_h;
    float* xbuf  = (float*)p_x;
    float* ctx   = (float*)p_ctx;
    float* mumix = (float*)p_mumix;

    geom_kernel<<<(NE + 255) / 256, 256>>>(r_ij);
    init_kernel<<<(NA * 3 * FF + 255) / 256, 256>>>(z, embedding, q, mu);

    for (int l = 0; l < NL; l++) {
        // h = silu(q @ W1 + b1)
        sgemm_kernel<<<dim3(128 / 64, (NA + 63) / 64), 256>>>(
            q, inter_W1 + (size_t)l * 128 * 128, inter_b1 + l * 128, hbuf, NA, 128, 128, 1);
        // x = h @ W2 + b2
        sgemm_kernel<<<dim3(384 / 64, (NA + 63) / 64), 256>>>(
            hbuf, inter_W2 + (size_t)l * 128 * 384, inter_b2 + l * 384, xbuf, NA, 384, 128, 0);
        // fused filters + edge messages: q += dq (atomics), g_dmu += dmu (atomics, reads old mu)
        edge_kernel<<<2368, 128>>>(filt_W, filt_b, l, idx_i, idx_j, mu, q);
        // mu += dmu; dmu = 0
        addmu_kernel<<<(NA * 3 * FF + 255) / 256, 256>>>(mu);
        // mu_mix = mu @ mix_W + mix_b   (45000 x 256)
        sgemm_kernel<<<dim3(256 / 64, (NA * 3 + 63) / 64), 256>>>(
            mu, mix_W + (size_t)l * 128 * 256, mix_b + l * 256, mumix, NA * 3, 256, 128, 0);
        // ctx = [q, ||mu_V||]
        ctx_kernel<<<(NA * FF + 255) / 256, 256>>>(q);
        // h = silu(ctx @ intra_W1 + b1)
        sgemm_kernel<<<dim3(128 / 64, (NA + 63) / 64), 256>>>(
            ctx, intra_W1 + (size_t)l * 256 * 128, intra_b1 + l * 128, hbuf, NA, 128, 256, 1);
        // x = h @ intra_W2 + b2
        sgemm_kernel<<<dim3(384 / 64, (NA + 63) / 64), 256>>>(
            hbuf, intra_W2 + (size_t)l * 128 * 384, intra_b2 + l * 384, xbuf, NA, 384, 128, 0);
        // q += dq_intra + dqmu_intra ; mu += dmu_intra
        update_kernel<<<(NA * FF + 255) / 256, 256>>>(q, mu);
    }
}